// round 1
// baseline (speedup 1.0000x reference)
#include <cuda_runtime.h>
#include <cstdint>

#define NB 16384
#define NV 1024
#define NH 1024
#define NC 64
#define NSTEPS 25

// JAX PRNG indexing scheme: 1 = jax_threefry_partitionable (default since jax 0.4.36)
#define JAX_PARTITIONABLE 1

// ---------------------------------------------------------------------------
// Scratch (static __device__ allocations; no cudaMalloc anywhere)
// ---------------------------------------------------------------------------
__device__ float g_bmod[NB * NV];      // 64 MB
__device__ float g_cmod[NB * NH];      // 64 MB
__device__ float g_v[NB * NV];         // 64 MB  (current v, 0/1 as float)
__device__ float g_h[NB * NH];         // 64 MB
__device__ float g_WT[NH * NV];        // 4 MB   (W transposed)
__device__ float g_fe_d[NB];
__device__ float g_fe_m[NB];
__device__ float g_fep_d[NB * 8];      // per-(row, colblock) softplus partials
__device__ float g_fep_m[NB * 8];

// ---------------------------------------------------------------------------
// threefry2x32 (exact JAX semantics)
// ---------------------------------------------------------------------------
__host__ __device__ __forceinline__ void threefry(uint32_t k0, uint32_t k1,
                                                  uint32_t x0, uint32_t x1,
                                                  uint32_t& o0, uint32_t& o1)
{
    uint32_t ks2 = k0 ^ k1 ^ 0x1BD11BDAu;
#define TF_ROT(x, r) (((x) << (r)) | ((x) >> (32 - (r))))
#define TF_RND(r) { x0 += x1; x1 = TF_ROT(x1, r); x1 ^= x0; }
    x0 += k0; x1 += k1;
    TF_RND(13) TF_RND(15) TF_RND(26) TF_RND(6)
    x0 += k1; x1 += ks2 + 1u;
    TF_RND(17) TF_RND(29) TF_RND(16) TF_RND(24)
    x0 += ks2; x1 += k0 + 2u;
    TF_RND(13) TF_RND(15) TF_RND(26) TF_RND(6)
    x0 += k0; x1 += k1 + 3u;
    TF_RND(17) TF_RND(29) TF_RND(16) TF_RND(24)
    x0 += k1; x1 += ks2 + 4u;
    TF_RND(13) TF_RND(15) TF_RND(26) TF_RND(6)
    x0 += ks2; x1 += k0 + 5u;
    o0 = x0; o1 = x1;
#undef TF_RND
#undef TF_ROT
}

// uniform [0,1) for flat element idx of a 16M-element draw
__device__ __forceinline__ float urand(uint32_t k0, uint32_t k1, uint32_t idx)
{
    uint32_t a, b;
#if JAX_PARTITIONABLE
    threefry(k0, k1, 0u, idx, a, b);
    uint32_t bits = a ^ b;
#else
    const uint32_t half = (uint32_t)(NB) * 1024u / 2u;  // 8388608
    uint32_t bits;
    if (idx < half) { threefry(k0, k1, idx, idx + half, a, b); bits = a; }
    else            { threefry(k0, k1, idx - half, idx, a, b); bits = b; }
#endif
    return __uint_as_float((bits >> 9) | 0x3F800000u) - 1.0f;
}

// ---------------------------------------------------------------------------
// Transpose W (V x H) -> g_WT (H x V)
// ---------------------------------------------------------------------------
__global__ void transpose_kernel(const float* __restrict__ W)
{
    __shared__ float t[32][33];
    int bx = blockIdx.x * 32;   // H tile
    int by = blockIdx.y * 32;   // V tile
    int tx = threadIdx.x, ty = threadIdx.y;  // 32 x 8
    #pragma unroll
    for (int i = 0; i < 32; i += 8)
        t[ty + i][tx] = W[(size_t)(by + ty + i) * NH + bx + tx];
    __syncthreads();
    #pragma unroll
    for (int i = 0; i < 32; i += 8)
        g_WT[(size_t)(bx + ty + i) * NV + by + tx] = t[tx][ty + i];
}

// ---------------------------------------------------------------------------
// Conditioning MLP -> b_mod, c_mod   (8 rows per block)
// ---------------------------------------------------------------------------
#define PROWS 8
__global__ void params_kernel(const float* __restrict__ cond, const float* __restrict__ b,
                              const float* __restrict__ c, const float* __restrict__ W1,
                              const float* __restrict__ b1, const float* __restrict__ W2,
                              const float* __restrict__ b2)
{
    __shared__ float sc[PROWS][NC];
    __shared__ float st[PROWS][NC];
    int row0 = blockIdx.x * PROWS;
    int tid = threadIdx.x;  // 256

    for (int i = tid; i < PROWS * NC; i += 256)
        sc[i / NC][i % NC] = cond[(size_t)(row0 + i / NC) * NC + (i % NC)];
    __syncthreads();
    for (int i = tid; i < PROWS * NC; i += 256) {
        int r = i / NC, j = i % NC;
        float s = b1[j];
        #pragma unroll 8
        for (int k = 0; k < NC; k++) s += sc[r][k] * W1[k * NC + j];
        st[r][j] = tanhf(s);
    }
    __syncthreads();

    // b_mod: params cols [q] (gamma_b) and [NV+q] (beta_b)
    for (int q = tid; q < NV; q += 256) {
        float ga[PROWS], be[PROWS];
        float ig = b2[q], ib = b2[NV + q];
        #pragma unroll
        for (int r = 0; r < PROWS; r++) { ga[r] = ig; be[r] = ib; }
        for (int k = 0; k < NC; k++) {
            float wg = W2[(size_t)k * 4096 + q];
            float wb = W2[(size_t)k * 4096 + NV + q];
            #pragma unroll
            for (int r = 0; r < PROWS; r++) { ga[r] += st[r][k] * wg; be[r] += st[r][k] * wb; }
        }
        float bq = b[q];
        #pragma unroll
        for (int r = 0; r < PROWS; r++)
            g_bmod[(size_t)(row0 + r) * NV + q] = (1.0f + ga[r]) * bq + be[r];
    }
    // c_mod: params cols [2*NV+q] (gamma_c) and [2*NV+NH+q] (beta_c)
    for (int q = tid; q < NH; q += 256) {
        float ga[PROWS], be[PROWS];
        float ig = b2[2 * NV + q], ib = b2[2 * NV + NH + q];
        #pragma unroll
        for (int r = 0; r < PROWS; r++) { ga[r] = ig; be[r] = ib; }
        for (int k = 0; k < NC; k++) {
            float wg = W2[(size_t)k * 4096 + 2 * NV + q];
            float wb = W2[(size_t)k * 4096 + 2 * NV + NH + q];
            #pragma unroll
            for (int r = 0; r < PROWS; r++) { ga[r] += st[r][k] * wg; be[r] += st[r][k] * wb; }
        }
        float cq = c[q];
        #pragma unroll
        for (int r = 0; r < PROWS; r++)
            g_cmod[(size_t)(row0 + r) * NH + q] = (1.0f + ga[r]) * cq + be[r];
    }
}

// ---------------------------------------------------------------------------
// v_start = bernoulli(k_start, 0.5)
// ---------------------------------------------------------------------------
__global__ void init_v_kernel(uint32_t k0, uint32_t k1)
{
    uint32_t i = blockIdx.x * blockDim.x + threadIdx.x;  // 16M threads
    float u = urand(k0, k1, i);
    g_v[i] = (u < 0.5f) ? 1.0f : 0.0f;
}

// ---------------------------------------------------------------------------
// Fused GEMM:  Z = A (M x 1024) @ Bm (1024 x 1024) + bias(row,col)
//   MODE 0: Out[row,col] = (uniform(key, idx) < sigmoid(Z)) ? 1 : 0
//   MODE 1: fe_part[row*8 + bx] = sum_cols softplus(Z)   (per 128-col block)
// Tiles 128x128x8, 256 threads, 8x8 per thread.
// ---------------------------------------------------------------------------
template <int MODE>
__global__ void __launch_bounds__(256, 2)
gemm_fused_kernel(const float* __restrict__ A, const float* __restrict__ Bm,
                  const float* __restrict__ bias, float* __restrict__ Out,
                  float* __restrict__ fe_part, uint32_t k0, uint32_t k1)
{
    __shared__ float As[8][128];
    __shared__ float Bs[8][128];

    const int tid = threadIdx.x;
    const int bx = blockIdx.x;          // 0..7   (N blocks)
    const int by = blockIdx.y;          // 0..127 (M blocks)
    const int m0 = by * 128, n0 = bx * 128;
    const int tx = tid & 15, ty = tid >> 4;

    const int arow = tid >> 1;          // 0..127
    const int acol = (tid & 1) * 4;     // 0 or 4
    const int brow = tid >> 5;          // 0..7
    const int bcol = (tid & 31) * 4;    // 0..124

    float acc[8][8];
    #pragma unroll
    for (int i = 0; i < 8; i++)
        #pragma unroll
        for (int j = 0; j < 8; j++) acc[i][j] = 0.0f;

    for (int kk = 0; kk < 1024; kk += 8) {
        float4 av = *(const float4*)(A + (size_t)(m0 + arow) * 1024 + kk + acol);
        float4 bv = *(const float4*)(Bm + (size_t)(kk + brow) * 1024 + n0 + bcol);
        __syncthreads();
        As[acol + 0][arow] = av.x; As[acol + 1][arow] = av.y;
        As[acol + 2][arow] = av.z; As[acol + 3][arow] = av.w;
        *(float4*)&Bs[brow][bcol] = bv;
        __syncthreads();
        #pragma unroll
        for (int p = 0; p < 8; p++) {
            float a[8], b[8];
            #pragma unroll
            for (int i = 0; i < 8; i++) a[i] = As[p][ty * 8 + i];
            #pragma unroll
            for (int j = 0; j < 8; j++) b[j] = Bs[p][tx * 8 + j];
            #pragma unroll
            for (int i = 0; i < 8; i++)
                #pragma unroll
                for (int j = 0; j < 8; j++) acc[i][j] += a[i] * b[j];
        }
    }

    #pragma unroll
    for (int i = 0; i < 8; i++) {
        int row = m0 + ty * 8 + i;
        const float4* bp = (const float4*)(bias + (size_t)row * 1024 + n0 + tx * 8);
        float4 b0 = bp[0], b1v = bp[1];
        float zb[8] = {b0.x, b0.y, b0.z, b0.w, b1v.x, b1v.y, b1v.z, b1v.w};
        if (MODE == 0) {
            uint32_t base = (uint32_t)(row * 1024 + n0 + tx * 8);
            float ov[8];
            #pragma unroll
            for (int j = 0; j < 8; j++) {
                float z = acc[i][j] + zb[j];
                float pz = 1.0f / (1.0f + expf(-z));
                float u = urand(k0, k1, base + (uint32_t)j);
                ov[j] = (u < pz) ? 1.0f : 0.0f;
            }
            float4* op = (float4*)(Out + (size_t)row * 1024 + n0 + tx * 8);
            op[0] = make_float4(ov[0], ov[1], ov[2], ov[3]);
            op[1] = make_float4(ov[4], ov[5], ov[6], ov[7]);
        } else {
            float s = 0.0f;
            #pragma unroll
            for (int j = 0; j < 8; j++) {
                float z = acc[i][j] + zb[j];
                s += fmaxf(z, 0.0f) + log1pf(expf(-fabsf(z)));  // softplus, JAX formula
            }
            // reduce across the 16 tx lanes (lane = (ty&1)*16 + tx)
            #pragma unroll
            for (int off = 8; off; off >>= 1)
                s += __shfl_down_sync(0xffffffffu, s, off, 16);
            if (tx == 0) fe_part[(size_t)row * 8 + bx] = s;
        }
    }
}

// ---------------------------------------------------------------------------
// fe[row] = -(v . bmod_row) - sum(fe_part[row, :])
// ---------------------------------------------------------------------------
__global__ void rowdot_kernel(const float* __restrict__ v, const float* __restrict__ bmod,
                              const float* __restrict__ part, float* __restrict__ fe)
{
    int row = blockIdx.x;
    int tid = threadIdx.x;  // 256
    float s = 0.0f;
    for (int q = tid; q < NV; q += 256)
        s += v[(size_t)row * NV + q] * bmod[(size_t)row * NV + q];
    __shared__ float red[8];
    #pragma unroll
    for (int off = 16; off; off >>= 1) s += __shfl_down_sync(0xffffffffu, s, off);
    if ((tid & 31) == 0) red[tid >> 5] = s;
    __syncthreads();
    if (tid == 0) {
        float d = 0.0f;
        #pragma unroll
        for (int w = 0; w < 8; w++) d += red[w];
        float sp = 0.0f;
        #pragma unroll
        for (int j = 0; j < 8; j++) sp += part[(size_t)row * 8 + j];
        fe[row] = -d - sp;
    }
}

// ---------------------------------------------------------------------------
// loss = mean(fe_d - fe_m)
// ---------------------------------------------------------------------------
__global__ void final_kernel(float* __restrict__ out)
{
    int tid = threadIdx.x;  // 256
    double s = 0.0;
    for (int i = tid; i < NB; i += 256)
        s += (double)g_fe_d[i] - (double)g_fe_m[i];
    __shared__ double red[8];
    #pragma unroll
    for (int off = 16; off; off >>= 1) s += __shfl_down_sync(0xffffffffu, s, off);
    if ((tid & 31) == 0) red[tid >> 5] = s;
    __syncthreads();
    if (tid == 0) {
        double t = 0.0;
        #pragma unroll
        for (int w = 0; w < 8; w++) t += red[w];
        out[0] = (float)(t / (double)NB);
    }
}

// ---------------------------------------------------------------------------
// Host orchestration
// ---------------------------------------------------------------------------
static void host_split_keys(uint32_t& sk0, uint32_t& sk1,
                            uint32_t* kh0, uint32_t* kh1,
                            uint32_t* kv0, uint32_t* kv1)
{
    // root key = jax.random.key(42) -> (0, 42)
    uint32_t rk0 = 0u, rk1 = 42u;
    uint32_t ck0, ck1;
#if JAX_PARTITIONABLE
    // split(root): keys[i] = tf(root, (0, i))
    threefry(rk0, rk1, 0u, 0u, ck0, ck1);  // k_chain
    threefry(rk0, rk1, 0u, 1u, sk0, sk1);  // k_start
    uint32_t k0 = ck0, k1 = ck1;
    for (int s = 0; s < NSTEPS; s++) {
        uint32_t nk0, nk1;
        threefry(k0, k1, 0u, 0u, nk0, nk1);        // new carry key
        threefry(k0, k1, 0u, 1u, kh0[s], kh1[s]);  // kh
        threefry(k0, k1, 0u, 2u, kv0[s], kv1[s]);  // kv
        k0 = nk0; k1 = nk1;
    }
#else
    // legacy split: counts iota(2n), halves -> pairs, concat, reshape (n,2)
    {
        uint32_t a0, a1, b0, b1;
        threefry(rk0, rk1, 0u, 2u, a0, a1);   // pair (0,2)
        threefry(rk0, rk1, 1u, 3u, b0, b1);   // pair (1,3)
        ck0 = a0; ck1 = b0;                    // k_chain = (y0(p0), y0(p1))
        sk0 = a1; sk1 = b1;                    // k_start = (y1(p0), y1(p1))
    }
    uint32_t k0 = ck0, k1 = ck1;
    for (int s = 0; s < NSTEPS; s++) {
        uint32_t y00, y10, y01, y11, y02, y12;
        threefry(k0, k1, 0u, 3u, y00, y10);   // pair (0,3)
        threefry(k0, k1, 1u, 4u, y01, y11);   // pair (1,4)
        threefry(k0, k1, 2u, 5u, y02, y12);   // pair (2,5)
        // flat = [y00,y01,y02,y10,y11,y12] -> keys (3,2)
        uint32_t nk0 = y00, nk1 = y01;
        kh0[s] = y02; kh1[s] = y10;
        kv0[s] = y11; kv1[s] = y12;
        k0 = nk0; k1 = nk1;
    }
#endif
}

extern "C" void kernel_launch(void* const* d_in, const int* in_sizes, int n_in,
                              void* d_out, int out_size)
{
    const float* v_data = (const float*)d_in[0];
    const float* cond   = (const float*)d_in[1];
    const float* W      = (const float*)d_in[2];
    const float* b      = (const float*)d_in[3];
    const float* c      = (const float*)d_in[4];
    const float* W1     = (const float*)d_in[5];
    const float* b1     = (const float*)d_in[6];
    const float* W2     = (const float*)d_in[7];
    const float* b2     = (const float*)d_in[8];
    float* out = (float*)d_out;

    uint32_t sk0, sk1;
    uint32_t kh0[NSTEPS], kh1[NSTEPS], kv0[NSTEPS], kv1[NSTEPS];
    host_split_keys(sk0, sk1, kh0, kh1, kv0, kv1);

    float *p_bmod, *p_cmod, *p_v, *p_h, *p_WT, *p_fed, *p_fem, *p_fpd, *p_fpm;
    cudaGetSymbolAddress((void**)&p_bmod, g_bmod);
    cudaGetSymbolAddress((void**)&p_cmod, g_cmod);
    cudaGetSymbolAddress((void**)&p_v, g_v);
    cudaGetSymbolAddress((void**)&p_h, g_h);
    cudaGetSymbolAddress((void**)&p_WT, g_WT);
    cudaGetSymbolAddress((void**)&p_fed, g_fe_d);
    cudaGetSymbolAddress((void**)&p_fem, g_fe_m);
    cudaGetSymbolAddress((void**)&p_fpd, g_fep_d);
    cudaGetSymbolAddress((void**)&p_fpm, g_fep_m);

    // 1. transpose W
    transpose_kernel<<<dim3(32, 32), dim3(32, 8)>>>(W);
    // 2. conditioning MLP -> b_mod, c_mod
    params_kernel<<<NB / PROWS, 256>>>(cond, b, c, W1, b1, W2, b2);
    // 3. v_start
    init_v_kernel<<<(NB * NV) / 256, 256>>>(sk0, sk1);
    // 4. Gibbs chain
    dim3 ggrid(8, 128);
    for (int s = 0; s < NSTEPS; s++) {
        gemm_fused_kernel<0><<<ggrid, 256>>>(p_v, W,    p_cmod, p_h, nullptr, kh0[s], kh1[s]);
        gemm_fused_kernel<0><<<ggrid, 256>>>(p_h, p_WT, p_bmod, p_v, nullptr, kv0[s], kv1[s]);
    }
    // 5. free energy: softplus row-sums via FE-mode GEMMs (deterministic partials)
    gemm_fused_kernel<1><<<ggrid, 256>>>(v_data, W, p_cmod, nullptr, p_fpd, 0u, 0u);
    gemm_fused_kernel<1><<<ggrid, 256>>>(p_v,    W, p_cmod, nullptr, p_fpm, 0u, 0u);
    rowdot_kernel<<<NB, 256>>>(v_data, p_bmod, p_fpd, p_fed);
    rowdot_kernel<<<NB, 256>>>(p_v,    p_bmod, p_fpm, p_fem);
    // 6. loss
    final_kernel<<<1, 256>>>(out);
}

// round 3
// speedup vs baseline: 4.3398x; 4.3398x over previous
#include <cuda_runtime.h>
#include <cuda_bf16.h>
#include <cstdint>

#define NB 16384
#define NV 1024
#define NH 1024
#define NC 64
#define NSTEPS 25

// ---------------------------------------------------------------------------
// Scratch (static __device__ allocations; no cudaMalloc anywhere)
// ---------------------------------------------------------------------------
__device__ float g_bmod[NB * NV];               // 64 MB
__device__ float g_cmod[NB * NH];               // 64 MB
__device__ __nv_bfloat16 g_v[NB * NV];          // 32 MB (current v, 0/1)
__device__ __nv_bfloat16 g_h[NB * NH];          // 32 MB
__device__ __nv_bfloat16 g_vd[NB * NV];         // 32 MB (v_data as bf16)
__device__ __nv_bfloat16 g_Wb1[NV * NH];        // W bf16 hi split (row-major [V][H])
__device__ __nv_bfloat16 g_Wb2[NV * NH];        // W bf16 lo split
__device__ __nv_bfloat16 g_WTb1[NH * NV];       // W^T splits ([H][V])
__device__ __nv_bfloat16 g_WTb2[NH * NV];
__device__ float g_fe_d[NB];
__device__ float g_fe_m[NB];
__device__ float g_fep_d[NB * 16];              // per-(row, 64-col block) softplus partials
__device__ float g_fep_m[NB * 16];

// ---------------------------------------------------------------------------
// threefry2x32 (exact JAX semantics, jax_threefry_partitionable)
// ---------------------------------------------------------------------------
__host__ __device__ __forceinline__ void threefry(uint32_t k0, uint32_t k1,
                                                  uint32_t x0, uint32_t x1,
                                                  uint32_t& o0, uint32_t& o1)
{
    uint32_t ks2 = k0 ^ k1 ^ 0x1BD11BDAu;
#define TF_ROT(x, r) (((x) << (r)) | ((x) >> (32 - (r))))
#define TF_RND(r) { x0 += x1; x1 = TF_ROT(x1, r); x1 ^= x0; }
    x0 += k0; x1 += k1;
    TF_RND(13) TF_RND(15) TF_RND(26) TF_RND(6)
    x0 += k1; x1 += ks2 + 1u;
    TF_RND(17) TF_RND(29) TF_RND(16) TF_RND(24)
    x0 += ks2; x1 += k0 + 2u;
    TF_RND(13) TF_RND(15) TF_RND(26) TF_RND(6)
    x0 += k0; x1 += k1 + 3u;
    TF_RND(17) TF_RND(29) TF_RND(16) TF_RND(24)
    x0 += k1; x1 += ks2 + 4u;
    TF_RND(13) TF_RND(15) TF_RND(26) TF_RND(6)
    x0 += ks2; x1 += k0 + 5u;
    o0 = x0; o1 = x1;
#undef TF_RND
#undef TF_ROT
}

__device__ __forceinline__ float urand(uint32_t k0, uint32_t k1, uint32_t idx)
{
    uint32_t a, b;
    threefry(k0, k1, 0u, idx, a, b);
    uint32_t bits = a ^ b;
    return __uint_as_float((bits >> 9) | 0x3F800000u) - 1.0f;
}

// ---------------------------------------------------------------------------
// MMA / ldmatrix / cp.async helpers (baseline PTX, legal on plain sm_103)
// ---------------------------------------------------------------------------
__device__ __forceinline__ uint32_t smem_u32(const void* p) {
    uint32_t a;
    asm("{ .reg .u64 t; cvta.to.shared.u64 t, %1; cvt.u32.u64 %0, t; }" : "=r"(a) : "l"(p));
    return a;
}
__device__ __forceinline__ void ldsm4(uint32_t* r, uint32_t addr) {
    asm volatile("ldmatrix.sync.aligned.m8n8.x4.shared.b16 {%0,%1,%2,%3}, [%4];"
                 : "=r"(r[0]), "=r"(r[1]), "=r"(r[2]), "=r"(r[3]) : "r"(addr));
}
__device__ __forceinline__ void mma16816(float* d, const uint32_t* a, uint32_t b0, uint32_t b1) {
    asm volatile("mma.sync.aligned.m16n8k16.row.col.f32.bf16.bf16.f32 "
                 "{%0,%1,%2,%3}, {%4,%5,%6,%7}, {%8,%9}, {%0,%1,%2,%3};"
                 : "+f"(d[0]), "+f"(d[1]), "+f"(d[2]), "+f"(d[3])
                 : "r"(a[0]), "r"(a[1]), "r"(a[2]), "r"(a[3]), "r"(b0), "r"(b1));
}
#define CP_ASYNC16(dst, src) \
    asm volatile("cp.async.cg.shared.global [%0], [%1], 16;" :: "r"(dst), "l"(src))
#define CP_COMMIT() asm volatile("cp.async.commit_group;")
#define CP_WAIT1()  asm volatile("cp.async.wait_group 1;")
#define CP_WAIT0()  asm volatile("cp.async.wait_group 0;")

__device__ __forceinline__ uint32_t swz(uint32_t off) {  // SW128 on 128B rows
    return off ^ ((off >> 3) & 0x70);
}

// ---------------------------------------------------------------------------
// W -> 2-way bf16 splits, row-major + transposed
// ---------------------------------------------------------------------------
__global__ void split_kernel(const float* __restrict__ W)
{
    __shared__ __nv_bfloat16 t1[32][33], t2[32][33];
    int bx = blockIdx.x * 32;   // h
    int by = blockIdx.y * 32;   // v
    int tx = threadIdx.x, ty = threadIdx.y;  // 32 x 8
    #pragma unroll
    for (int i = 0; i < 32; i += 8) {
        float w = W[(size_t)(by + ty + i) * NH + bx + tx];
        __nv_bfloat16 h1 = __float2bfloat16(w);
        float r = w - __bfloat162float(h1);
        __nv_bfloat16 h2 = __float2bfloat16(r);
        size_t o = (size_t)(by + ty + i) * NH + bx + tx;
        g_Wb1[o] = h1; g_Wb2[o] = h2;
        t1[ty + i][tx] = h1; t2[ty + i][tx] = h2;
    }
    __syncthreads();
    #pragma unroll
    for (int i = 0; i < 32; i += 8) {
        size_t o = (size_t)(bx + ty + i) * NV + by + tx;
        g_WTb1[o] = t1[tx][ty + i]; g_WTb2[o] = t2[tx][ty + i];
    }
}

// ---------------------------------------------------------------------------
// Conditioning MLP -> b_mod, c_mod
// ---------------------------------------------------------------------------
#define PROWS 8
__global__ void params_kernel(const float* __restrict__ cond, const float* __restrict__ b,
                              const float* __restrict__ c, const float* __restrict__ W1,
                              const float* __restrict__ b1, const float* __restrict__ W2,
                              const float* __restrict__ b2)
{
    __shared__ float sc[PROWS][NC];
    __shared__ float st[PROWS][NC];
    int row0 = blockIdx.x * PROWS;
    int tid = threadIdx.x;  // 256

    for (int i = tid; i < PROWS * NC; i += 256)
        sc[i / NC][i % NC] = cond[(size_t)(row0 + i / NC) * NC + (i % NC)];
    __syncthreads();
    for (int i = tid; i < PROWS * NC; i += 256) {
        int r = i / NC, j = i % NC;
        float s = b1[j];
        #pragma unroll 8
        for (int k = 0; k < NC; k++) s += sc[r][k] * W1[k * NC + j];
        st[r][j] = tanhf(s);
    }
    __syncthreads();

    for (int q = tid; q < NV; q += 256) {
        float ga[PROWS], be[PROWS];
        float ig = b2[q], ib = b2[NV + q];
        #pragma unroll
        for (int r = 0; r < PROWS; r++) { ga[r] = ig; be[r] = ib; }
        for (int k = 0; k < NC; k++) {
            float wg = W2[(size_t)k * 4096 + q];
            float wb = W2[(size_t)k * 4096 + NV + q];
            #pragma unroll
            for (int r = 0; r < PROWS; r++) { ga[r] += st[r][k] * wg; be[r] += st[r][k] * wb; }
        }
        float bq = b[q];
        #pragma unroll
        for (int r = 0; r < PROWS; r++)
            g_bmod[(size_t)(row0 + r) * NV + q] = (1.0f + ga[r]) * bq + be[r];
    }
    for (int q = tid; q < NH; q += 256) {
        float ga[PROWS], be[PROWS];
        float ig = b2[2 * NV + q], ib = b2[2 * NV + NH + q];
        #pragma unroll
        for (int r = 0; r < PROWS; r++) { ga[r] = ig; be[r] = ib; }
        for (int k = 0; k < NC; k++) {
            float wg = W2[(size_t)k * 4096 + 2 * NV + q];
            float wb = W2[(size_t)k * 4096 + 2 * NV + NH + q];
            #pragma unroll
            for (int r = 0; r < PROWS; r++) { ga[r] += st[r][k] * wg; be[r] += st[r][k] * wb; }
        }
        float cq = c[q];
        #pragma unroll
        for (int r = 0; r < PROWS; r++)
            g_cmod[(size_t)(row0 + r) * NH + q] = (1.0f + ga[r]) * cq + be[r];
    }
}

// ---------------------------------------------------------------------------
// v_start = bernoulli(k_start, 0.5) as bf16; v_data -> bf16
// ---------------------------------------------------------------------------
__global__ void init_v_kernel(uint32_t k0, uint32_t k1)
{
    uint32_t i = blockIdx.x * blockDim.x + threadIdx.x;
    float u = urand(k0, k1, i);
    g_v[i] = __float2bfloat16((u < 0.5f) ? 1.0f : 0.0f);
}
__global__ void conv_vdata_kernel(const float* __restrict__ vd)
{
    uint32_t i = blockIdx.x * blockDim.x + threadIdx.x;
    g_vd[i] = __float2bfloat16(vd[i]);
}

// ---------------------------------------------------------------------------
// mma.sync fused GEMM: Z[128x128 tile] = A @ (B1+B2)^T_mma + bias
//   MODE 0: Out = bernoulli(sigmoid(Z))  (bf16 0/1)
//   MODE 1: fe_part[row*16 + bx*2 + half] = sum_{64 cols} softplus(Z)
// 2-stage cp.async pipeline, K-chunk 64, warps 2(M)x4(N), warp tile 64x32.
// ---------------------------------------------------------------------------
#define KCHUNK 64
#define STAGE_BYTES 49152        // A(16K) + B1(16K) + B2(16K)
#define SMEM_TOTAL (2 * STAGE_BYTES)

__device__ __forceinline__ void stage_load(uint32_t s_stage,
    const __nv_bfloat16* A, const __nv_bfloat16* B1, const __nv_bfloat16* B2,
    int m0, int n0, int kk, int tid)
{
    #pragma unroll
    for (int r = 0; r < 12; r++) {
        int i = tid + r * 256;          // 0..3071
        int buf = i >> 10;              // 0:A 1:B1 2:B2
        int row = (i >> 3) & 127;
        int ch  = i & 7;
        const char* src;
        if (buf == 0)      src = (const char*)A  + (size_t)(m0 + row) * 2048 + kk * 128 + ch * 16;
        else if (buf == 1) src = (const char*)B1 + (size_t)(n0 + row) * 2048 + kk * 128 + ch * 16;
        else               src = (const char*)B2 + (size_t)(n0 + row) * 2048 + kk * 128 + ch * 16;
        uint32_t off = (uint32_t)(row * 128 + ch * 16);
        CP_ASYNC16(s_stage + buf * 16384 + swz(off), src);
    }
    CP_COMMIT();
}

template <int MODE>
__global__ void __launch_bounds__(256, 2)
mma_gibbs_kernel(const __nv_bfloat16* __restrict__ A,
                 const __nv_bfloat16* __restrict__ B1,
                 const __nv_bfloat16* __restrict__ B2,
                 const float* __restrict__ bias,
                 __nv_bfloat16* __restrict__ Out,
                 float* __restrict__ fe_part,
                 uint32_t k0, uint32_t k1)
{
    extern __shared__ char smem[];
    const uint32_t sbase = smem_u32(smem);
    const int tid = threadIdx.x;
    const int wid = tid >> 5, lane = tid & 31;
    const int warp_m = wid & 1;          // 0..1 -> 64-row halves
    const int warp_n = wid >> 1;         // 0..3 -> 32-col quarters
    const int m0 = blockIdx.y * 128;
    const int n0 = blockIdx.x * 128;

    float acc[4][4][4];                  // [mt(16m)][n8][frag]
    #pragma unroll
    for (int i = 0; i < 4; i++)
        #pragma unroll
        for (int j = 0; j < 4; j++)
            #pragma unroll
            for (int q = 0; q < 4; q++) acc[i][j][q] = 0.0f;

    stage_load(sbase, A, B1, B2, m0, n0, 0, tid);

    const int la = lane & 15, ha = lane >> 4;

    for (int kk = 0; kk < 16; kk++) {
        const uint32_t s = sbase + (uint32_t)(kk & 1) * STAGE_BYTES;
        if (kk + 1 < 16) {
            stage_load(sbase + (uint32_t)((kk + 1) & 1) * STAGE_BYTES, A, B1, B2, m0, n0, kk + 1, tid);
            CP_WAIT1();
        } else {
            CP_WAIT0();
        }
        __syncthreads();

        #pragma unroll
        for (int ks = 0; ks < 4; ks++) {
            uint32_t a[4][4];
            #pragma unroll
            for (int mt = 0; mt < 4; mt++) {
                uint32_t off = (uint32_t)((warp_m * 64 + mt * 16 + la) * 128 + ks * 32 + ha * 16);
                ldsm4(a[mt], s + swz(off));
            }
            #pragma unroll
            for (int sp = 0; sp < 2; sp++) {
                uint32_t b[2][4];
                #pragma unroll
                for (int g = 0; g < 2; g++) {
                    uint32_t off = (uint32_t)((warp_n * 32 + g * 16 + la) * 128 + ks * 32 + ha * 16);
                    ldsm4(b[g], s + 16384u * (1 + sp) + swz(off));
                }
                #pragma unroll
                for (int mt = 0; mt < 4; mt++)
                    #pragma unroll
                    for (int n8 = 0; n8 < 4; n8++)
                        mma16816(acc[mt][n8], a[mt], b[n8 >> 1][n8 & 1], b[n8 >> 1][(n8 & 1) + 2]);
            }
        }
        __syncthreads();
    }

    // Spill Z to smem (stride 132 floats to dodge bank conflicts)
    float* zs = (float*)smem;
    #pragma unroll
    for (int mt = 0; mt < 4; mt++)
        #pragma unroll
        for (int n8 = 0; n8 < 4; n8++) {
            int r = warp_m * 64 + mt * 16 + (lane >> 2);
            int c = warp_n * 32 + n8 * 8 + (lane & 3) * 2;
            zs[r * 132 + c]           = acc[mt][n8][0];
            zs[r * 132 + c + 1]       = acc[mt][n8][1];
            zs[(r + 8) * 132 + c]     = acc[mt][n8][2];
            zs[(r + 8) * 132 + c + 1] = acc[mt][n8][3];
        }
    __syncthreads();

    // Per-thread epilogue: row = tid>>1 (local), 64-col half = tid&1
    const int rloc = tid >> 1;
    const int c0 = (tid & 1) * 64;
    const int row = m0 + rloc;
    const float* zrow = zs + rloc * 132 + c0;
    const float4* bp = (const float4*)(bias + (size_t)row * 1024 + n0 + c0);

    if (MODE == 0) {
        const uint32_t ibase = (uint32_t)(row * 1024 + n0 + c0);
        uint4* op = (uint4*)(Out + (size_t)row * 1024 + n0 + c0);
        #pragma unroll 1
        for (int j0 = 0; j0 < 64; j0 += 8) {
            float4 bv0 = bp[j0 / 4], bv1 = bp[j0 / 4 + 1];
            float zb[8] = {bv0.x, bv0.y, bv0.z, bv0.w, bv1.x, bv1.y, bv1.z, bv1.w};
            uint32_t pk[4];
            #pragma unroll
            for (int jj = 0; jj < 8; jj += 2) {
                float z0 = zrow[j0 + jj] + zb[jj];
                float z1 = zrow[j0 + jj + 1] + zb[jj + 1];
                float e0 = __expf(-z0), e1 = __expf(-z1);
                float u0 = urand(k0, k1, ibase + (uint32_t)(j0 + jj));
                float u1 = urand(k0, k1, ibase + (uint32_t)(j0 + jj) + 1u);
                uint32_t s0 = (fmaf(u0, e0, u0) < 1.0f) ? 0x3F80u : 0u;
                uint32_t s1 = (fmaf(u1, e1, u1) < 1.0f) ? 0x3F80u : 0u;
                pk[jj >> 1] = s0 | (s1 << 16);
            }
            op[j0 / 8] = make_uint4(pk[0], pk[1], pk[2], pk[3]);
        }
    } else {
        float sp_acc = 0.0f;
        #pragma unroll 1
        for (int j0 = 0; j0 < 64; j0 += 8) {
            float4 bv0 = bp[j0 / 4], bv1 = bp[j0 / 4 + 1];
            float zb[8] = {bv0.x, bv0.y, bv0.z, bv0.w, bv1.x, bv1.y, bv1.z, bv1.w};
            #pragma unroll
            for (int jj = 0; jj < 8; jj++) {
                float z = zrow[j0 + jj] + zb[jj];
                sp_acc += fmaxf(z, 0.0f) + log1pf(expf(-fabsf(z)));
            }
        }
        fe_part[(size_t)row * 16 + blockIdx.x * 2 + (tid & 1)] = sp_acc;
    }
}

// ---------------------------------------------------------------------------
// fe[row] = -(v . bmod_row) - sum(fe_part[row, :16])
// ---------------------------------------------------------------------------
__global__ void rowdot_kernel(const __nv_bfloat16* __restrict__ v, const float* __restrict__ bmod,
                              const float* __restrict__ part, float* __restrict__ fe)
{
    int row = blockIdx.x;
    int tid = threadIdx.x;  // 256
    float s = 0.0f;
    for (int q = tid; q < NV; q += 256)
        s += __bfloat162float(v[(size_t)row * NV + q]) * bmod[(size_t)row * NV + q];
    __shared__ float red[8];
    #pragma unroll
    for (int off = 16; off; off >>= 1) s += __shfl_down_sync(0xffffffffu, s, off);
    if ((tid & 31) == 0) red[tid >> 5] = s;
    __syncthreads();
    if (tid == 0) {
        float dsum = 0.0f;
        #pragma unroll
        for (int w = 0; w < 8; w++) dsum += red[w];
        float sp = 0.0f;
        #pragma unroll
        for (int j = 0; j < 16; j++) sp += part[(size_t)row * 16 + j];
        fe[row] = -dsum - sp;
    }
}

__global__ void final_kernel(float* __restrict__ out)
{
    int tid = threadIdx.x;  // 256
    double s = 0.0;
    for (int i = tid; i < NB; i += 256)
        s += (double)g_fe_d[i] - (double)g_fe_m[i];
    __shared__ double red[8];
    #pragma unroll
    for (int off = 16; off; off >>= 1) s += __shfl_down_sync(0xffffffffu, s, off);
    if ((tid & 31) == 0) red[tid >> 5] = s;
    __syncthreads();
    if (tid == 0) {
        double t = 0.0;
        #pragma unroll
        for (int w = 0; w < 8; w++) t += red[w];
        out[0] = (float)(t / (double)NB);
    }
}

// ---------------------------------------------------------------------------
// Host orchestration
// ---------------------------------------------------------------------------
static void host_split_keys(uint32_t& sk0, uint32_t& sk1,
                            uint32_t* kh0, uint32_t* kh1,
                            uint32_t* kv0, uint32_t* kv1)
{
    uint32_t rk0 = 0u, rk1 = 42u;
    uint32_t ck0, ck1;
    threefry(rk0, rk1, 0u, 0u, ck0, ck1);  // k_chain
    threefry(rk0, rk1, 0u, 1u, sk0, sk1);  // k_start
    uint32_t k0 = ck0, k1 = ck1;
    for (int s = 0; s < NSTEPS; s++) {
        uint32_t nk0, nk1;
        threefry(k0, k1, 0u, 0u, nk0, nk1);
        threefry(k0, k1, 0u, 1u, kh0[s], kh1[s]);
        threefry(k0, k1, 0u, 2u, kv0[s], kv1[s]);
        k0 = nk0; k1 = nk1;
    }
}

extern "C" void kernel_launch(void* const* d_in, const int* in_sizes, int n_in,
                              void* d_out, int out_size)
{
    const float* v_data = (const float*)d_in[0];
    const float* cond   = (const float*)d_in[1];
    const float* W      = (const float*)d_in[2];
    const float* b      = (const float*)d_in[3];
    const float* c      = (const float*)d_in[4];
    const float* W1     = (const float*)d_in[5];
    const float* b1     = (const float*)d_in[6];
    const float* W2     = (const float*)d_in[7];
    const float* b2     = (const float*)d_in[8];
    float* out = (float*)d_out;

    uint32_t sk0, sk1;
    uint32_t kh0[NSTEPS], kh1[NSTEPS], kv0[NSTEPS], kv1[NSTEPS];
    host_split_keys(sk0, sk1, kh0, kh1, kv0, kv1);

    cudaFuncSetAttribute(mma_gibbs_kernel<0>, cudaFuncAttributeMaxDynamicSharedMemorySize, SMEM_TOTAL);
    cudaFuncSetAttribute(mma_gibbs_kernel<1>, cudaFuncAttributeMaxDynamicSharedMemorySize, SMEM_TOTAL);

    __nv_bfloat16 *p_v, *p_h, *p_vd, *p_Wb1, *p_Wb2, *p_WT1, *p_WT2;
    float *p_bmod, *p_cmod, *p_fed, *p_fem, *p_fpd, *p_fpm;
    cudaGetSymbolAddress((void**)&p_v, g_v);
    cudaGetSymbolAddress((void**)&p_h, g_h);
    cudaGetSymbolAddress((void**)&p_vd, g_vd);
    cudaGetSymbolAddress((void**)&p_Wb1, g_Wb1);
    cudaGetSymbolAddress((void**)&p_Wb2, g_Wb2);
    cudaGetSymbolAddress((void**)&p_WT1, g_WTb1);
    cudaGetSymbolAddress((void**)&p_WT2, g_WTb2);
    cudaGetSymbolAddress((void**)&p_bmod, g_bmod);
    cudaGetSymbolAddress((void**)&p_cmod, g_cmod);
    cudaGetSymbolAddress((void**)&p_fed, g_fe_d);
    cudaGetSymbolAddress((void**)&p_fem, g_fe_m);
    cudaGetSymbolAddress((void**)&p_fpd, g_fep_d);
    cudaGetSymbolAddress((void**)&p_fpm, g_fep_m);

    split_kernel<<<dim3(32, 32), dim3(32, 8)>>>(W);
    params_kernel<<<NB / PROWS, 256>>>(cond, b, c, W1, b1, W2, b2);
    init_v_kernel<<<(NB * NV) / 256, 256>>>(sk0, sk1);
    conv_vdata_kernel<<<(NB * NV) / 256, 256>>>(v_data);

    dim3 ggrid(8, 128);
    for (int s = 0; s < NSTEPS; s++) {
        // h = bern(sigmoid(v @ W + c_mod)); B operand = W^T splits
        mma_gibbs_kernel<0><<<ggrid, 256, SMEM_TOTAL>>>(
            p_v, p_WT1, p_WT2, p_cmod, p_h, nullptr, kh0[s], kh1[s]);
        // v = bern(sigmoid(h @ W^T + b_mod)); B operand = W splits
        mma_gibbs_kernel<0><<<ggrid, 256, SMEM_TOTAL>>>(
            p_h, p_Wb1, p_Wb2, p_bmod, p_v, nullptr, kv0[s], kv1[s]);
    }
    // free-energy softplus partials
    mma_gibbs_kernel<1><<<ggrid, 256, SMEM_TOTAL>>>(
        p_vd, p_WT1, p_WT2, p_cmod, nullptr, p_fpd, 0u, 0u);
    mma_gibbs_kernel<1><<<ggrid, 256, SMEM_TOTAL>>>(
        p_v, p_WT1, p_WT2, p_cmod, nullptr, p_fpm, 0u, 0u);
    rowdot_kernel<<<NB, 256>>>(p_vd, p_bmod, p_fpd, p_fed);
    rowdot_kernel<<<NB, 256>>>(p_v, p_bmod, p_fpm, p_fem);
    final_kernel<<<1, 256>>>(out);
}